// round 10
// baseline (speedup 1.0000x reference)
#include <cuda_runtime.h>
#include <cuda_bf16.h>
#include <math.h>
#include <stdint.h>

// Problem dims
#define Bv     16
#define Sv     2048
#define Hv     1024
#define NSPAN  64
#define NROW   (Bv * NSPAN)   // 1024
#define NCLS   4096

// ArcFace constants
#define SCALE_F 30.0f
#define COS_M_F 0.8775825618903728f
#define SIN_M_F 0.479425538604203f
#define TH_F    (-0.8775825618903728f)
#define MM_F    0.2397127693021015f

// Scratch
__device__ __nv_bfloat16 g_emb[NROW * Hv];     // 2 MB
__device__ __nv_bfloat16 g_w[NCLS * Hv];       // 8 MB
__device__ float         g_sumexp[NROW];
__device__ float         g_llab[NROW];

// ---------------------------------------------------------------------------
__device__ __forceinline__ float block_sum256(float v) {
    __shared__ float buf[8];
    #pragma unroll
    for (int o = 16; o; o >>= 1) v += __shfl_xor_sync(0xffffffffu, v, o);
    int t = threadIdx.x;
    if ((t & 31) == 0) buf[t >> 5] = v;
    __syncthreads();
    float r;
    if (t < 32) {
        float x = (t < 8) ? buf[t] : 0.0f;
        #pragma unroll
        for (int o = 4; o; o >>= 1) x += __shfl_xor_sync(0xffffffffu, x, o);
        if (t == 0) buf[0] = x;
    }
    __syncthreads();
    r = buf[0];
    __syncthreads();
    return r;
}

// ---------------------------------------------------------------------------
// Kernel 1 (merged prep). Heavy span blocks first; span gather unrolled x8.
// ---------------------------------------------------------------------------
__global__ void prep_kernel(const float* __restrict__ enc,
                            const float* __restrict__ gamma,
                            const float* __restrict__ beta,
                            const float* __restrict__ w,
                            const int*   __restrict__ heads,
                            const int*   __restrict__ tails) {
    const int t = threadIdx.x;
    if (blockIdx.x < NROW) {
        const int row = blockIdx.x;
        if (row < 4) g_sumexp[row * 256 + t] = 0.0f;
        const int b   = row >> 6;
        const int head = heads[row];
        const int tail = tails[row];
        const float inv_len = 1.0f / (float)(tail - head);

        const float4* base = (const float4*)(enc + (size_t)b * Sv * Hv);
        const int RW = Hv / 4;

        float4 a = make_float4(0.f, 0.f, 0.f, 0.f);
        int r = head;
        for (; r + 7 < tail; r += 8) {
            float4 x0 = base[(size_t)(r + 0) * RW + t];
            float4 x1 = base[(size_t)(r + 1) * RW + t];
            float4 x2 = base[(size_t)(r + 2) * RW + t];
            float4 x3 = base[(size_t)(r + 3) * RW + t];
            float4 x4 = base[(size_t)(r + 4) * RW + t];
            float4 x5 = base[(size_t)(r + 5) * RW + t];
            float4 x6 = base[(size_t)(r + 6) * RW + t];
            float4 x7 = base[(size_t)(r + 7) * RW + t];
            a.x += ((x0.x + x1.x) + (x2.x + x3.x)) + ((x4.x + x5.x) + (x6.x + x7.x));
            a.y += ((x0.y + x1.y) + (x2.y + x3.y)) + ((x4.y + x5.y) + (x6.y + x7.y));
            a.z += ((x0.z + x1.z) + (x2.z + x3.z)) + ((x4.z + x5.z) + (x6.z + x7.z));
            a.w += ((x0.w + x1.w) + (x2.w + x3.w)) + ((x4.w + x5.w) + (x6.w + x7.w));
        }
        if (r + 3 < tail) {
            float4 x0 = base[(size_t)(r + 0) * RW + t];
            float4 x1 = base[(size_t)(r + 1) * RW + t];
            float4 x2 = base[(size_t)(r + 2) * RW + t];
            float4 x3 = base[(size_t)(r + 3) * RW + t];
            a.x += (x0.x + x1.x) + (x2.x + x3.x);
            a.y += (x0.y + x1.y) + (x2.y + x3.y);
            a.z += (x0.z + x1.z) + (x2.z + x3.z);
            a.w += (x0.w + x1.w) + (x2.w + x3.w);
            r += 4;
        }
        for (; r < tail; ++r) {
            const float4 x = base[(size_t)r * RW + t];
            a.x += x.x; a.y += x.y; a.z += x.z; a.w += x.w;
        }
        a.x *= inv_len; a.y *= inv_len; a.z *= inv_len; a.w *= inv_len;

        const float s  = a.x + a.y + a.z + a.w;
        const float s2 = a.x * a.x + a.y * a.y + a.z * a.z + a.w * a.w;
        const float mu   = block_sum256(s)  * (1.0f / Hv);
        const float ex2  = block_sum256(s2) * (1.0f / Hv);
        const float rstd = rsqrtf(ex2 - mu * mu + 1e-7f);

        const float4 gm = ((const float4*)gamma)[t];
        const float4 bt = ((const float4*)beta)[t];
        float y0 = (a.x - mu) * rstd * gm.x + bt.x;
        float y1 = (a.y - mu) * rstd * gm.y + bt.y;
        float y2 = (a.z - mu) * rstd * gm.z + bt.z;
        float y3 = (a.w - mu) * rstd * gm.w + bt.w;

        const float yn2 = y0 * y0 + y1 * y1 + y2 * y2 + y3 * y3;
        const float nrm = sqrtf(block_sum256(yn2));
        const float inv = 1.0f / fmaxf(nrm, 1e-12f);

        __nv_bfloat162* o2 = (__nv_bfloat162*)(g_emb + (size_t)row * Hv);
        o2[2 * t]     = __floats2bfloat162_rn(y0 * inv, y1 * inv);
        o2[2 * t + 1] = __floats2bfloat162_rn(y2 * inv, y3 * inv);
    } else {
        const int row = blockIdx.x - NROW;
        const float4 v = ((const float4*)(w + (size_t)row * Hv))[t];
        const float s2 = v.x * v.x + v.y * v.y + v.z * v.z + v.w * v.w;
        const float nrm = sqrtf(block_sum256(s2));
        const float inv = 1.0f / fmaxf(nrm, 1e-12f);
        __nv_bfloat162* o2 = (__nv_bfloat162*)(g_w + (size_t)row * Hv);
        o2[2 * t]     = __floats2bfloat162_rn(v.x * inv, v.y * inv);
        o2[2 * t + 1] = __floats2bfloat162_rn(v.z * inv, v.w * inv);
    }
}

// ---------------------------------------------------------------------------
// Kernel 2: GEMM [1024x4096] K=1024 bf16 mma.sync + fused ArcFace/softmax.
// 128(M) x 256(N) tile, grid 16x8 = 128 blocks (single wave).
// 256 threads: 2m x 4n warps, warp tile 64x64. BK=64, 3-stage cp.async,
// single barrier per k-iteration, ldmatrix.x4 fragment loads.
// ---------------------------------------------------------------------------
#define BM 128
#define BN 256
#define BK 64
#define NST 3
#define KT (Hv / BK)          // 16
#define STR 72                // bf16 row stride (144B = 36 words, conflict-free)
#define STAGE_BYTES ((BM + BN) * STR * 2)   // 55296
#define GEMM_SMEM (NST * STAGE_BYTES)       // 165888

__device__ __forceinline__ void cp_async16(uint32_t saddr, const void* gmem) {
    asm volatile("cp.async.cg.shared.global [%0], [%1], 16;\n" :: "r"(saddr), "l"(gmem));
}
#define CP_COMMIT asm volatile("cp.async.commit_group;\n" ::: "memory")
template <int N>
__device__ __forceinline__ void cp_wait() {
    asm volatile("cp.async.wait_group %0;\n" :: "n"(N) : "memory");
}

__device__ __forceinline__ void ldsm_x4(uint32_t r[4], uint32_t saddr) {
    asm volatile("ldmatrix.sync.aligned.m8n8.x4.shared.b16 {%0,%1,%2,%3}, [%4];\n"
                 : "=r"(r[0]), "=r"(r[1]), "=r"(r[2]), "=r"(r[3]) : "r"(saddr));
}

__device__ __forceinline__ void mma16816(float c[4], const uint32_t a[4],
                                         const uint32_t b0, const uint32_t b1) {
    asm volatile(
        "mma.sync.aligned.m16n8k16.row.col.f32.bf16.bf16.f32 "
        "{%0,%1,%2,%3}, {%4,%5,%6,%7}, {%8,%9}, {%0,%1,%2,%3};\n"
        : "+f"(c[0]), "+f"(c[1]), "+f"(c[2]), "+f"(c[3])
        : "r"(a[0]), "r"(a[1]), "r"(a[2]), "r"(a[3]), "r"(b0), "r"(b1));
}

extern __shared__ __nv_bfloat16 dynsmem[];

__global__ void __launch_bounds__(256, 1) gemm_fused_kernel(const int* __restrict__ labels) {
    __shared__ float rs[BM];

    const int tid  = threadIdx.x;
    const int wid  = tid >> 5;
    const int lane = tid & 31;
    const int bm = blockIdx.y * BM;
    const int bn = blockIdx.x * BN;
    const int wm = (wid & 1) * 64;     // warp m-offset (2 m-warps)
    const int wn = (wid >> 1) * 64;    // warp n-offset (4 n-warps)
    const int g   = lane >> 2;
    const int tig = lane & 3;

    const uint32_t smem_s = (uint32_t)__cvta_generic_to_shared(dynsmem);

    // cp.async staging: BK=64 rows of 128B = 8 chunks of 16B.
    // A: 128 rows * 8 = 1024 chunks (4/thread); B: 256 rows * 8 = 2048 (8/thread)
    const int srow = tid >> 3;        // 0..31
    const int scol = (tid & 7) * 8;   // bf16 col 0..56

    // ldmatrix per-lane offsets (bf16 units)
    const int a_row = wm + ((lane >> 3) & 1) * 8 + (lane & 7);
    const int a_col = (lane >> 4) * 8;
    const uint32_t a_off = (uint32_t)(a_row * STR + a_col) * 2;
    const int b_row = wn + (lane >> 4) * 8 + (lane & 7);
    const int b_col = ((lane >> 3) & 1) * 8;
    const uint32_t b_off = (uint32_t)((BM + b_row) * STR + b_col) * 2;

    float acc[4][8][4];
    #pragma unroll
    for (int mt = 0; mt < 4; ++mt)
        #pragma unroll
        for (int nt = 0; nt < 8; ++nt)
            #pragma unroll
            for (int i = 0; i < 4; ++i) acc[mt][nt][i] = 0.f;

    auto load_stage = [&](int stage, int kt) {
        const uint32_t base = smem_s + stage * STAGE_BYTES;
        const int k0 = kt * BK;
        #pragma unroll
        for (int j = 0; j < 4; ++j)
            cp_async16(base + (uint32_t)((srow + 32 * j) * STR + scol) * 2,
                       &g_emb[(size_t)(bm + srow + 32 * j) * Hv + k0 + scol]);
        #pragma unroll
        for (int j = 0; j < 8; ++j)
            cp_async16(base + (uint32_t)((BM + srow + 32 * j) * STR + scol) * 2,
                       &g_w[(size_t)(bn + srow + 32 * j) * Hv + k0 + scol]);
        CP_COMMIT;
    };

    // prologue: stages 0,1
    load_stage(0, 0);
    load_stage(1, 1);

    for (int kt = 0; kt < KT; ++kt) {
        if (kt == KT - 1) cp_wait<0>();
        else              cp_wait<1>();
        __syncthreads();                 // single barrier per iteration
        if (kt + 2 < KT) load_stage((kt + 2) % NST, kt + 2);

        const uint32_t sbase = smem_s + (kt % NST) * STAGE_BYTES;
        #pragma unroll
        for (int kk = 0; kk < BK; kk += 16) {
            uint32_t afr[4][4], bfr[4][4];
            #pragma unroll
            for (int mt = 0; mt < 4; ++mt)
                ldsm_x4(afr[mt], sbase + a_off + (mt * 16 * STR + kk) * 2);
            #pragma unroll
            for (int bt = 0; bt < 4; ++bt)
                ldsm_x4(bfr[bt], sbase + b_off + (bt * 16 * STR + kk) * 2);
            #pragma unroll
            for (int mt = 0; mt < 4; ++mt)
                #pragma unroll
                for (int bt = 0; bt < 4; ++bt) {
                    mma16816(acc[mt][2 * bt + 0], afr[mt], bfr[bt][0], bfr[bt][1]);
                    mma16816(acc[mt][2 * bt + 1], afr[mt], bfr[bt][2], bfr[bt][3]);
                }
        }
    }
    __syncthreads();

    // ---------------- fused ArcFace + partial softmax epilogue ----------------
    if (tid < BM) rs[tid] = 0.0f;
    __syncthreads();

    #pragma unroll
    for (int mt = 0; mt < 4; ++mt) {
        const int rl1 = wm + mt * 16 + g;
        const int rl2 = rl1 + 8;
        const int gr1 = bm + rl1;
        const int gr2 = bm + rl2;
        const int lab1 = labels[gr1];
        const int lab2 = labels[gr2];

        float s1 = 0.f, s2 = 0.f;
        #pragma unroll
        for (int nt = 0; nt < 8; ++nt) {
            const int c0 = bn + wn + nt * 8 + 2 * tig;
            #pragma unroll
            for (int e = 0; e < 2; ++e) {
                const int c = c0 + e;
                {
                    const float cs = acc[mt][nt][e];
                    float l = cs * SCALE_F;
                    if (c == lab1) {
                        const float sine = sqrtf(fmaxf(1.0f - cs * cs, 0.0f));
                        float phi = cs * COS_M_F - sine * SIN_M_F;
                        phi = (cs > TH_F) ? phi : (cs - MM_F);
                        l = phi * SCALE_F;
                        g_llab[gr1] = l;
                    }
                    s1 += __expf(l - SCALE_F);
                }
                {
                    const float cs = acc[mt][nt][2 + e];
                    float l = cs * SCALE_F;
                    if (c == lab2) {
                        const float sine = sqrtf(fmaxf(1.0f - cs * cs, 0.0f));
                        float phi = cs * COS_M_F - sine * SIN_M_F;
                        phi = (cs > TH_F) ? phi : (cs - MM_F);
                        l = phi * SCALE_F;
                        g_llab[gr2] = l;
                    }
                    s2 += __expf(l - SCALE_F);
                }
            }
        }
        #pragma unroll
        for (int o = 1; o <= 2; o <<= 1) {
            s1 += __shfl_xor_sync(0xffffffffu, s1, o);
            s2 += __shfl_xor_sync(0xffffffffu, s2, o);
        }
        if (tig == 0) {
            atomicAdd(&rs[rl1], s1);
            atomicAdd(&rs[rl2], s2);
        }
    }
    __syncthreads();
    if (tid < BM) atomicAdd(&g_sumexp[bm + tid], rs[tid]);
}

// ---------------------------------------------------------------------------
// Kernel 3: nll per row + mean -> out[0]
// ---------------------------------------------------------------------------
__global__ void final_kernel(float* __restrict__ out) {
    const int t = threadIdx.x;
    float s = 0.f;
    for (int i = t; i < NROW; i += 256)
        s += (SCALE_F + logf(g_sumexp[i])) - g_llab[i];
    const float tot = block_sum256(s);
    if (t == 0) out[0] = tot * (1.0f / NROW);
}

// ---------------------------------------------------------------------------
extern "C" void kernel_launch(void* const* d_in, const int* in_sizes, int n_in,
                              void* d_out, int out_size) {
    const float* enc   = (const float*)d_in[0];
    const float* gamma = (const float*)d_in[1];
    const float* beta  = (const float*)d_in[2];
    const float* w     = (const float*)d_in[3];
    const int* heads   = (const int*)d_in[4];
    const int* tails   = (const int*)d_in[5];
    const int* labels  = (const int*)d_in[6];
    float* out = (float*)d_out;

    prep_kernel<<<NCLS + NROW, 256>>>(enc, gamma, beta, w, heads, tails);

    cudaFuncSetAttribute(gemm_fused_kernel,
                         cudaFuncAttributeMaxDynamicSharedMemorySize, GEMM_SMEM);
    dim3 ggrid(NCLS / BN, NROW / BM);   // (16, 8) = 128 blocks, one wave
    gemm_fused_kernel<<<ggrid, 256, GEMM_SMEM>>>(labels);

    final_kernel<<<1, 256>>>(out);
}

// round 11
// speedup vs baseline: 1.0501x; 1.0501x over previous
#include <cuda_runtime.h>
#include <cuda_bf16.h>
#include <math.h>
#include <stdint.h>

// Problem dims
#define Bv     16
#define Sv     2048
#define Hv     1024
#define NSPAN  64
#define NROW   (Bv * NSPAN)   // 1024
#define NCLS   4096

// ArcFace constants
#define SCALE_F 30.0f
#define COS_M_F 0.8775825618903728f
#define SIN_M_F 0.479425538604203f
#define TH_F    (-0.8775825618903728f)
#define MM_F    0.2397127693021015f

// Scratch
__device__ __nv_bfloat16 g_emb[NROW * Hv];     // 2 MB
__device__ __nv_bfloat16 g_w[NCLS * Hv];       // 8 MB
__device__ float         g_sumexp[NROW];
__device__ float         g_llab[NROW];

// ---------------------------------------------------------------------------
__device__ __forceinline__ float block_sum256(float v) {
    __shared__ float buf[8];
    #pragma unroll
    for (int o = 16; o; o >>= 1) v += __shfl_xor_sync(0xffffffffu, v, o);
    int t = threadIdx.x;
    if ((t & 31) == 0) buf[t >> 5] = v;
    __syncthreads();
    float r;
    if (t < 32) {
        float x = (t < 8) ? buf[t] : 0.0f;
        #pragma unroll
        for (int o = 4; o; o >>= 1) x += __shfl_xor_sync(0xffffffffu, x, o);
        if (t == 0) buf[0] = x;
    }
    __syncthreads();
    r = buf[0];
    __syncthreads();
    return r;
}

// ---------------------------------------------------------------------------
// Kernel 1 (merged prep). Heavy span blocks first; span gather unrolled x8.
// ---------------------------------------------------------------------------
__global__ void prep_kernel(const float* __restrict__ enc,
                            const float* __restrict__ gamma,
                            const float* __restrict__ beta,
                            const float* __restrict__ w,
                            const int*   __restrict__ heads,
                            const int*   __restrict__ tails) {
    const int t = threadIdx.x;
    if (blockIdx.x < NROW) {
        const int row = blockIdx.x;
        if (row < 4) g_sumexp[row * 256 + t] = 0.0f;
        const int b   = row >> 6;
        const int head = heads[row];
        const int tail = tails[row];
        const float inv_len = 1.0f / (float)(tail - head);

        const float4* base = (const float4*)(enc + (size_t)b * Sv * Hv);
        const int RW = Hv / 4;

        float4 a = make_float4(0.f, 0.f, 0.f, 0.f);
        int r = head;
        for (; r + 7 < tail; r += 8) {
            float4 x0 = base[(size_t)(r + 0) * RW + t];
            float4 x1 = base[(size_t)(r + 1) * RW + t];
            float4 x2 = base[(size_t)(r + 2) * RW + t];
            float4 x3 = base[(size_t)(r + 3) * RW + t];
            float4 x4 = base[(size_t)(r + 4) * RW + t];
            float4 x5 = base[(size_t)(r + 5) * RW + t];
            float4 x6 = base[(size_t)(r + 6) * RW + t];
            float4 x7 = base[(size_t)(r + 7) * RW + t];
            a.x += ((x0.x + x1.x) + (x2.x + x3.x)) + ((x4.x + x5.x) + (x6.x + x7.x));
            a.y += ((x0.y + x1.y) + (x2.y + x3.y)) + ((x4.y + x5.y) + (x6.y + x7.y));
            a.z += ((x0.z + x1.z) + (x2.z + x3.z)) + ((x4.z + x5.z) + (x6.z + x7.z));
            a.w += ((x0.w + x1.w) + (x2.w + x3.w)) + ((x4.w + x5.w) + (x6.w + x7.w));
        }
        if (r + 3 < tail) {
            float4 x0 = base[(size_t)(r + 0) * RW + t];
            float4 x1 = base[(size_t)(r + 1) * RW + t];
            float4 x2 = base[(size_t)(r + 2) * RW + t];
            float4 x3 = base[(size_t)(r + 3) * RW + t];
            a.x += (x0.x + x1.x) + (x2.x + x3.x);
            a.y += (x0.y + x1.y) + (x2.y + x3.y);
            a.z += (x0.z + x1.z) + (x2.z + x3.z);
            a.w += (x0.w + x1.w) + (x2.w + x3.w);
            r += 4;
        }
        for (; r < tail; ++r) {
            const float4 x = base[(size_t)r * RW + t];
            a.x += x.x; a.y += x.y; a.z += x.z; a.w += x.w;
        }
        a.x *= inv_len; a.y *= inv_len; a.z *= inv_len; a.w *= inv_len;

        const float s  = a.x + a.y + a.z + a.w;
        const float s2 = a.x * a.x + a.y * a.y + a.z * a.z + a.w * a.w;
        const float mu   = block_sum256(s)  * (1.0f / Hv);
        const float ex2  = block_sum256(s2) * (1.0f / Hv);
        const float rstd = rsqrtf(ex2 - mu * mu + 1e-7f);

        const float4 gm = ((const float4*)gamma)[t];
        const float4 bt = ((const float4*)beta)[t];
        float y0 = (a.x - mu) * rstd * gm.x + bt.x;
        float y1 = (a.y - mu) * rstd * gm.y + bt.y;
        float y2 = (a.z - mu) * rstd * gm.z + bt.z;
        float y3 = (a.w - mu) * rstd * gm.w + bt.w;

        const float yn2 = y0 * y0 + y1 * y1 + y2 * y2 + y3 * y3;
        const float nrm = sqrtf(block_sum256(yn2));
        const float inv = 1.0f / fmaxf(nrm, 1e-12f);

        __nv_bfloat162* o2 = (__nv_bfloat162*)(g_emb + (size_t)row * Hv);
        o2[2 * t]     = __floats2bfloat162_rn(y0 * inv, y1 * inv);
        o2[2 * t + 1] = __floats2bfloat162_rn(y2 * inv, y3 * inv);
    } else {
        const int row = blockIdx.x - NROW;
        const float4 v = ((const float4*)(w + (size_t)row * Hv))[t];
        const float s2 = v.x * v.x + v.y * v.y + v.z * v.z + v.w * v.w;
        const float nrm = sqrtf(block_sum256(s2));
        const float inv = 1.0f / fmaxf(nrm, 1e-12f);
        __nv_bfloat162* o2 = (__nv_bfloat162*)(g_w + (size_t)row * Hv);
        o2[2 * t]     = __floats2bfloat162_rn(v.x * inv, v.y * inv);
        o2[2 * t + 1] = __floats2bfloat162_rn(v.z * inv, v.w * inv);
    }
}

// ---------------------------------------------------------------------------
// Kernel 2: GEMM [1024x4096] K=1024 bf16 mma.sync + fused ArcFace/softmax.
// 128(M) x 256(N) tile, grid 16x8 = 128 blocks (single wave).
// 512 threads: 4m x 4n warps, warp tile 32x64. BK=64, 3-stage cp.async,
// SINGLE barrier per k-iteration, ldmatrix.x4 fragment loads.
// ---------------------------------------------------------------------------
#define BM 128
#define BN 256
#define BK 64
#define NST 3
#define KT (Hv / BK)          // 16
#define STR 72                // bf16 row stride (144B = 36 words, conflict-free)
#define STAGE_BYTES ((BM + BN) * STR * 2)   // 55296
#define GEMM_SMEM (NST * STAGE_BYTES)       // 165888

__device__ __forceinline__ void cp_async16(uint32_t saddr, const void* gmem) {
    asm volatile("cp.async.cg.shared.global [%0], [%1], 16;\n" :: "r"(saddr), "l"(gmem));
}
#define CP_COMMIT asm volatile("cp.async.commit_group;\n" ::: "memory")
template <int N>
__device__ __forceinline__ void cp_wait() {
    asm volatile("cp.async.wait_group %0;\n" :: "n"(N) : "memory");
}

__device__ __forceinline__ void ldsm_x4(uint32_t r[4], uint32_t saddr) {
    asm volatile("ldmatrix.sync.aligned.m8n8.x4.shared.b16 {%0,%1,%2,%3}, [%4];\n"
                 : "=r"(r[0]), "=r"(r[1]), "=r"(r[2]), "=r"(r[3]) : "r"(saddr));
}

__device__ __forceinline__ void mma16816(float c[4], const uint32_t a[4],
                                         const uint32_t b0, const uint32_t b1) {
    asm volatile(
        "mma.sync.aligned.m16n8k16.row.col.f32.bf16.bf16.f32 "
        "{%0,%1,%2,%3}, {%4,%5,%6,%7}, {%8,%9}, {%0,%1,%2,%3};\n"
        : "+f"(c[0]), "+f"(c[1]), "+f"(c[2]), "+f"(c[3])
        : "r"(a[0]), "r"(a[1]), "r"(a[2]), "r"(a[3]), "r"(b0), "r"(b1));
}

extern __shared__ __nv_bfloat16 dynsmem[];

__global__ void __launch_bounds__(512, 1) gemm_fused_kernel(const int* __restrict__ labels) {
    __shared__ float rs[BM];

    const int tid  = threadIdx.x;
    const int wid  = tid >> 5;
    const int lane = tid & 31;
    const int bm = blockIdx.y * BM;
    const int bn = blockIdx.x * BN;
    const int wm = (wid & 3) * 32;     // warp m-offset (4 m-warps)
    const int wn = (wid >> 2) * 64;    // warp n-offset (4 n-warps)
    const int g   = lane >> 2;
    const int tig = lane & 3;

    const uint32_t smem_s = (uint32_t)__cvta_generic_to_shared(dynsmem);

    // cp.async staging: BK=64 rows of 128B = 8 chunks of 16B.
    // A: 1024 chunks (2/thread); B: 2048 chunks (4/thread)
    const int srow = tid >> 3;        // 0..63
    const int scol = (tid & 7) * 8;   // bf16 col 0..56
    const uint32_t sa_off0 = (uint32_t)((srow      ) * STR + scol) * 2;
    const uint32_t sa_off1 = (uint32_t)((srow +  64) * STR + scol) * 2;
    const uint32_t sb_off0 = (uint32_t)((BM + srow      ) * STR + scol) * 2;
    const uint32_t sb_off1 = (uint32_t)((BM + srow +  64) * STR + scol) * 2;
    const uint32_t sb_off2 = (uint32_t)((BM + srow + 128) * STR + scol) * 2;
    const uint32_t sb_off3 = (uint32_t)((BM + srow + 192) * STR + scol) * 2;

    // ldmatrix per-lane offsets (bf16 units)
    const int a_row = wm + ((lane >> 3) & 1) * 8 + (lane & 7);
    const int a_col = (lane >> 4) * 8;
    const uint32_t a_off = (uint32_t)(a_row * STR + a_col) * 2;
    const int b_row = wn + (lane >> 4) * 8 + (lane & 7);
    const int b_col = ((lane >> 3) & 1) * 8;
    const uint32_t b_off = (uint32_t)((BM + b_row) * STR + b_col) * 2;

    float acc[2][8][4];
    #pragma unroll
    for (int mt = 0; mt < 2; ++mt)
        #pragma unroll
        for (int nt = 0; nt < 8; ++nt)
            #pragma unroll
            for (int i = 0; i < 4; ++i) acc[mt][nt][i] = 0.f;

    auto load_stage = [&](int stage, int kt) {
        const uint32_t base = smem_s + stage * STAGE_BYTES;
        const int k0 = kt * BK;
        cp_async16(base + sa_off0, &g_emb[(size_t)(bm + srow      ) * Hv + k0 + scol]);
        cp_async16(base + sa_off1, &g_emb[(size_t)(bm + srow +  64) * Hv + k0 + scol]);
        cp_async16(base + sb_off0, &g_w[(size_t)(bn + srow      ) * Hv + k0 + scol]);
        cp_async16(base + sb_off1, &g_w[(size_t)(bn + srow +  64) * Hv + k0 + scol]);
        cp_async16(base + sb_off2, &g_w[(size_t)(bn + srow + 128) * Hv + k0 + scol]);
        cp_async16(base + sb_off3, &g_w[(size_t)(bn + srow + 192) * Hv + k0 + scol]);
        CP_COMMIT;
    };

    // prologue: stages 0,1
    load_stage(0, 0);
    load_stage(1, 1);

    for (int kt = 0; kt < KT; ++kt) {
        if (kt == KT - 1) cp_wait<0>();
        else              cp_wait<1>();
        __syncthreads();                 // single barrier per iteration
        if (kt + 2 < KT) load_stage((kt + 2) % NST, kt + 2);

        const uint32_t sbase = smem_s + (kt % NST) * STAGE_BYTES;
        #pragma unroll
        for (int kk = 0; kk < BK; kk += 16) {
            uint32_t afr[2][4];
            ldsm_x4(afr[0], sbase + a_off + kk * 2);
            ldsm_x4(afr[1], sbase + a_off + (16 * STR + kk) * 2);
            uint32_t bfr[4][4];
            #pragma unroll
            for (int bt = 0; bt < 4; ++bt)
                ldsm_x4(bfr[bt], sbase + b_off + (bt * 16 * STR + kk) * 2);
            #pragma unroll
            for (int mt = 0; mt < 2; ++mt)
                #pragma unroll
                for (int bt = 0; bt < 4; ++bt) {
                    mma16816(acc[mt][2 * bt + 0], afr[mt], bfr[bt][0], bfr[bt][1]);
                    mma16816(acc[mt][2 * bt + 1], afr[mt], bfr[bt][2], bfr[bt][3]);
                }
        }
    }
    __syncthreads();

    // ---------------- fused ArcFace + partial softmax epilogue ----------------
    if (tid < BM) rs[tid] = 0.0f;
    __syncthreads();

    #pragma unroll
    for (int mt = 0; mt < 2; ++mt) {
        const int rl1 = wm + mt * 16 + g;
        const int rl2 = rl1 + 8;
        const int gr1 = bm + rl1;
        const int gr2 = bm + rl2;
        const int lab1 = labels[gr1];
        const int lab2 = labels[gr2];

        float s1 = 0.f, s2 = 0.f;
        #pragma unroll
        for (int nt = 0; nt < 8; ++nt) {
            const int c0 = bn + wn + nt * 8 + 2 * tig;
            #pragma unroll
            for (int e = 0; e < 2; ++e) {
                const int c = c0 + e;
                {
                    const float cs = acc[mt][nt][e];
                    float l = cs * SCALE_F;
                    if (c == lab1) {
                        const float sine = sqrtf(fmaxf(1.0f - cs * cs, 0.0f));
                        float phi = cs * COS_M_F - sine * SIN_M_F;
                        phi = (cs > TH_F) ? phi : (cs - MM_F);
                        l = phi * SCALE_F;
                        g_llab[gr1] = l;
                    }
                    s1 += __expf(l - SCALE_F);
                }
                {
                    const float cs = acc[mt][nt][2 + e];
                    float l = cs * SCALE_F;
                    if (c == lab2) {
                        const float sine = sqrtf(fmaxf(1.0f - cs * cs, 0.0f));
                        float phi = cs * COS_M_F - sine * SIN_M_F;
                        phi = (cs > TH_F) ? phi : (cs - MM_F);
                        l = phi * SCALE_F;
                        g_llab[gr2] = l;
                    }
                    s2 += __expf(l - SCALE_F);
                }
            }
        }
        #pragma unroll
        for (int o = 1; o <= 2; o <<= 1) {
            s1 += __shfl_xor_sync(0xffffffffu, s1, o);
            s2 += __shfl_xor_sync(0xffffffffu, s2, o);
        }
        if (tig == 0) {
            atomicAdd(&rs[rl1], s1);
            atomicAdd(&rs[rl2], s2);
        }
    }
    __syncthreads();
    if (tid < BM) atomicAdd(&g_sumexp[bm + tid], rs[tid]);
}

// ---------------------------------------------------------------------------
// Kernel 3: nll per row + mean -> out[0]
// ---------------------------------------------------------------------------
__global__ void final_kernel(float* __restrict__ out) {
    const int t = threadIdx.x;
    float s = 0.f;
    for (int i = t; i < NROW; i += 256)
        s += (SCALE_F + logf(g_sumexp[i])) - g_llab[i];
    const float tot = block_sum256(s);
    if (t == 0) out[0] = tot * (1.0f / NROW);
}

// ---------------------------------------------------------------------------
extern "C" void kernel_launch(void* const* d_in, const int* in_sizes, int n_in,
                              void* d_out, int out_size) {
    const float* enc   = (const float*)d_in[0];
    const float* gamma = (const float*)d_in[1];
    const float* beta  = (const float*)d_in[2];
    const float* w     = (const float*)d_in[3];
    const int* heads   = (const int*)d_in[4];
    const int* tails   = (const int*)d_in[5];
    const int* labels  = (const int*)d_in[6];
    float* out = (float*)d_out;

    prep_kernel<<<NCLS + NROW, 256>>>(enc, gamma, beta, w, heads, tails);

    cudaFuncSetAttribute(gemm_fused_kernel,
                         cudaFuncAttributeMaxDynamicSharedMemorySize, GEMM_SMEM);
    dim3 ggrid(NCLS / BN, NROW / BM);   // (16, 8) = 128 blocks, one wave
    gemm_fused_kernel<<<ggrid, 512, GEMM_SMEM>>>(labels);

    final_kernel<<<1, 256>>>(out);
}

// round 12
// speedup vs baseline: 1.0795x; 1.0281x over previous
#include <cuda_runtime.h>
#include <cuda_bf16.h>
#include <math.h>
#include <stdint.h>

// Problem dims
#define Bv     16
#define Sv     2048
#define Hv     1024
#define NSPAN  64
#define NROW   (Bv * NSPAN)   // 1024
#define NCLS   4096

// ArcFace constants
#define SCALE_F 30.0f
#define COS_M_F 0.8775825618903728f
#define SIN_M_F 0.479425538604203f
#define TH_F    (-0.8775825618903728f)
#define MM_F    0.2397127693021015f

// fp8 pre-scale: operands x32 each -> acc is 1024x cosine
#define QSCALE 32.0f
#define INV_QS2 (1.0f / 1024.0f)

// Scratch (fp8 operands)
__device__ uint8_t g_emb[NROW * Hv];     // 1 MB
__device__ uint8_t g_w[NCLS * Hv];       // 4 MB
__device__ float   g_sumexp[NROW];
__device__ float   g_llab[NROW];

// ---------------------------------------------------------------------------
__device__ __forceinline__ float block_sum256(float v) {
    __shared__ float buf[8];
    #pragma unroll
    for (int o = 16; o; o >>= 1) v += __shfl_xor_sync(0xffffffffu, v, o);
    int t = threadIdx.x;
    if ((t & 31) == 0) buf[t >> 5] = v;
    __syncthreads();
    float r;
    if (t < 32) {
        float x = (t < 8) ? buf[t] : 0.0f;
        #pragma unroll
        for (int o = 4; o; o >>= 1) x += __shfl_xor_sync(0xffffffffu, x, o);
        if (t == 0) buf[0] = x;
    }
    __syncthreads();
    r = buf[0];
    __syncthreads();
    return r;
}

// pack 4 floats -> 4 e4m3 bytes (consistent k-order for A and B)
__device__ __forceinline__ uint32_t pack_e4m3x4(float f0, float f1, float f2, float f3) {
    uint16_t lo, hi;
    asm("cvt.rn.satfinite.e4m3x2.f32 %0, %1, %2;" : "=h"(lo) : "f"(f1), "f"(f0));
    asm("cvt.rn.satfinite.e4m3x2.f32 %0, %1, %2;" : "=h"(hi) : "f"(f3), "f"(f2));
    return ((uint32_t)hi << 16) | lo;
}

// ---------------------------------------------------------------------------
// Kernel 1 (merged prep). Heavy span blocks first; span gather unrolled x8.
// Outputs e4m3 scaled by 32.
// ---------------------------------------------------------------------------
__global__ void prep_kernel(const float* __restrict__ enc,
                            const float* __restrict__ gamma,
                            const float* __restrict__ beta,
                            const float* __restrict__ w,
                            const int*   __restrict__ heads,
                            const int*   __restrict__ tails) {
    const int t = threadIdx.x;
    if (blockIdx.x < NROW) {
        const int row = blockIdx.x;
        if (row < 4) g_sumexp[row * 256 + t] = 0.0f;
        const int b   = row >> 6;
        const int head = heads[row];
        const int tail = tails[row];
        const float inv_len = 1.0f / (float)(tail - head);

        const float4* base = (const float4*)(enc + (size_t)b * Sv * Hv);
        const int RW = Hv / 4;

        float4 a = make_float4(0.f, 0.f, 0.f, 0.f);
        int r = head;
        for (; r + 7 < tail; r += 8) {
            float4 x0 = base[(size_t)(r + 0) * RW + t];
            float4 x1 = base[(size_t)(r + 1) * RW + t];
            float4 x2 = base[(size_t)(r + 2) * RW + t];
            float4 x3 = base[(size_t)(r + 3) * RW + t];
            float4 x4 = base[(size_t)(r + 4) * RW + t];
            float4 x5 = base[(size_t)(r + 5) * RW + t];
            float4 x6 = base[(size_t)(r + 6) * RW + t];
            float4 x7 = base[(size_t)(r + 7) * RW + t];
            a.x += ((x0.x + x1.x) + (x2.x + x3.x)) + ((x4.x + x5.x) + (x6.x + x7.x));
            a.y += ((x0.y + x1.y) + (x2.y + x3.y)) + ((x4.y + x5.y) + (x6.y + x7.y));
            a.z += ((x0.z + x1.z) + (x2.z + x3.z)) + ((x4.z + x5.z) + (x6.z + x7.z));
            a.w += ((x0.w + x1.w) + (x2.w + x3.w)) + ((x4.w + x5.w) + (x6.w + x7.w));
        }
        if (r + 3 < tail) {
            float4 x0 = base[(size_t)(r + 0) * RW + t];
            float4 x1 = base[(size_t)(r + 1) * RW + t];
            float4 x2 = base[(size_t)(r + 2) * RW + t];
            float4 x3 = base[(size_t)(r + 3) * RW + t];
            a.x += (x0.x + x1.x) + (x2.x + x3.x);
            a.y += (x0.y + x1.y) + (x2.y + x3.y);
            a.z += (x0.z + x1.z) + (x2.z + x3.z);
            a.w += (x0.w + x1.w) + (x2.w + x3.w);
            r += 4;
        }
        for (; r < tail; ++r) {
            const float4 x = base[(size_t)r * RW + t];
            a.x += x.x; a.y += x.y; a.z += x.z; a.w += x.w;
        }
        a.x *= inv_len; a.y *= inv_len; a.z *= inv_len; a.w *= inv_len;

        const float s  = a.x + a.y + a.z + a.w;
        const float s2 = a.x * a.x + a.y * a.y + a.z * a.z + a.w * a.w;
        const float mu   = block_sum256(s)  * (1.0f / Hv);
        const float ex2  = block_sum256(s2) * (1.0f / Hv);
        const float rstd = rsqrtf(ex2 - mu * mu + 1e-7f);

        const float4 gm = ((const float4*)gamma)[t];
        const float4 bt = ((const float4*)beta)[t];
        float y0 = (a.x - mu) * rstd * gm.x + bt.x;
        float y1 = (a.y - mu) * rstd * gm.y + bt.y;
        float y2 = (a.z - mu) * rstd * gm.z + bt.z;
        float y3 = (a.w - mu) * rstd * gm.w + bt.w;

        const float yn2 = y0 * y0 + y1 * y1 + y2 * y2 + y3 * y3;
        const float nrm = sqrtf(block_sum256(yn2));
        const float inv = QSCALE / fmaxf(nrm, 1e-12f);

        ((uint32_t*)(g_emb + (size_t)row * Hv))[t] =
            pack_e4m3x4(y0 * inv, y1 * inv, y2 * inv, y3 * inv);
    } else {
        const int row = blockIdx.x - NROW;
        const float4 v = ((const float4*)(w + (size_t)row * Hv))[t];
        const float s2 = v.x * v.x + v.y * v.y + v.z * v.z + v.w * v.w;
        const float nrm = sqrtf(block_sum256(s2));
        const float inv = QSCALE / fmaxf(nrm, 1e-12f);
        ((uint32_t*)(g_w + (size_t)row * Hv))[t] =
            pack_e4m3x4(v.x * inv, v.y * inv, v.z * inv, v.w * inv);
    }
}

// ---------------------------------------------------------------------------
// Kernel 2: FP8 GEMM [1024x4096] K=1024 (e4m3, m16n8k32) + fused ArcFace/
// softmax. 128(M) x 256(N) tile, grid 16x8 = 128 blocks (single wave).
// 512 threads: 4m x 4n warps, warp tile 32x64. BK=128 bytes, 3-stage
// cp.async, single barrier per k-iteration.
// ---------------------------------------------------------------------------
#define BM 128
#define BN 256
#define BKB 128                        // k-bytes (= elements) per iteration
#define NST 3
#define KT (Hv / BKB)                  // 8
#define STRB 144                       // bytes per smem row (128 + 16 pad)
#define STAGE_BYTES ((BM + BN) * STRB) // 55296
#define GEMM_SMEM (NST * STAGE_BYTES)  // 165888

__device__ __forceinline__ void cp_async16(uint32_t saddr, const void* gmem) {
    asm volatile("cp.async.cg.shared.global [%0], [%1], 16;\n" :: "r"(saddr), "l"(gmem));
}
#define CP_COMMIT asm volatile("cp.async.commit_group;\n" ::: "memory")
template <int N>
__device__ __forceinline__ void cp_wait() {
    asm volatile("cp.async.wait_group %0;\n" :: "n"(N) : "memory");
}

__device__ __forceinline__ void ldsm_x4(uint32_t r[4], uint32_t saddr) {
    asm volatile("ldmatrix.sync.aligned.m8n8.x4.shared.b16 {%0,%1,%2,%3}, [%4];\n"
                 : "=r"(r[0]), "=r"(r[1]), "=r"(r[2]), "=r"(r[3]) : "r"(saddr));
}

__device__ __forceinline__ void mma_fp8(float c[4], const uint32_t a[4],
                                        const uint32_t b0, const uint32_t b1) {
    asm volatile(
        "mma.sync.aligned.m16n8k32.row.col.f32.e4m3.e4m3.f32 "
        "{%0,%1,%2,%3}, {%4,%5,%6,%7}, {%8,%9}, {%0,%1,%2,%3};\n"
        : "+f"(c[0]), "+f"(c[1]), "+f"(c[2]), "+f"(c[3])
        : "r"(a[0]), "r"(a[1]), "r"(a[2]), "r"(a[3]), "r"(b0), "r"(b1));
}

extern __shared__ uint8_t dynsmem[];

__global__ void __launch_bounds__(512, 1) gemm_fused_kernel(const int* __restrict__ labels) {
    __shared__ float rs[BM];

    const int tid  = threadIdx.x;
    const int wid  = tid >> 5;
    const int lane = tid & 31;
    const int bm = blockIdx.y * BM;
    const int bn = blockIdx.x * BN;
    const int wm = (wid & 3) * 32;     // warp m-offset (4 m-warps)
    const int wn = (wid >> 2) * 64;    // warp n-offset (4 n-warps)
    const int g   = lane >> 2;
    const int tig = lane & 3;

    const uint32_t smem_s = (uint32_t)__cvta_generic_to_shared(dynsmem);

    // cp.async staging: each k-iter row = 128 B = 8 chunks of 16B.
    // A: 128 rows * 8 = 1024 chunks (2/thread); B: 256 rows * 8 = 2048 (4/thread)
    const int srow  = tid >> 3;         // 0..63
    const int scolb = (tid & 7) * 16;   // byte col 0..112
    const uint32_t sa_off0 = (uint32_t)((srow      ) * STRB + scolb);
    const uint32_t sa_off1 = (uint32_t)((srow +  64) * STRB + scolb);
    const uint32_t sb_off0 = (uint32_t)((BM + srow      ) * STRB + scolb);
    const uint32_t sb_off1 = (uint32_t)((BM + srow +  64) * STRB + scolb);
    const uint32_t sb_off2 = (uint32_t)((BM + srow + 128) * STRB + scolb);
    const uint32_t sb_off3 = (uint32_t)((BM + srow + 192) * STRB + scolb);

    // ldmatrix per-lane byte offsets
    // A (x4 over m16 x 32B): rows wm + ((lane>>3)&1)*8 + (lane&7), byte (lane>>4)*16
    const uint32_t a_off = (uint32_t)((wm + ((lane >> 3) & 1) * 8 + (lane & 7)) * STRB
                                      + (lane >> 4) * 16);
    // B (x4 over 4 n8-tiles at one 16B k-chunk): row wn + lane (n-half adds 32)
    const uint32_t b_off = (uint32_t)((BM + wn + lane) * STRB);

    float acc[2][8][4];
    #pragma unroll
    for (int mt = 0; mt < 2; ++mt)
        #pragma unroll
        for (int nt = 0; nt < 8; ++nt)
            #pragma unroll
            for (int i = 0; i < 4; ++i) acc[mt][nt][i] = 0.f;

    const uint8_t* gA = g_emb;
    const uint8_t* gB = g_w;

    auto load_stage = [&](int stage, int kt) {
        const uint32_t base = smem_s + stage * STAGE_BYTES;
        const int k0 = kt * BKB;
        cp_async16(base + sa_off0, &gA[(size_t)(bm + srow      ) * Hv + k0 + scolb]);
        cp_async16(base + sa_off1, &gA[(size_t)(bm + srow +  64) * Hv + k0 + scolb]);
        cp_async16(base + sb_off0, &gB[(size_t)(bn + srow      ) * Hv + k0 + scolb]);
        cp_async16(base + sb_off1, &gB[(size_t)(bn + srow +  64) * Hv + k0 + scolb]);
        cp_async16(base + sb_off2, &gB[(size_t)(bn + srow + 128) * Hv + k0 + scolb]);
        cp_async16(base + sb_off3, &gB[(size_t)(bn + srow + 192) * Hv + k0 + scolb]);
        CP_COMMIT;
    };

    // prologue: stages 0,1
    load_stage(0, 0);
    load_stage(1, 1);

    for (int kt = 0; kt < KT; ++kt) {
        if (kt == KT - 1) cp_wait<0>();
        else              cp_wait<1>();
        __syncthreads();                 // single barrier per iteration
        if (kt + 2 < KT) load_stage((kt + 2) % NST, kt + 2);

        const uint32_t sbase = smem_s + (kt % NST) * STAGE_BYTES;
        #pragma unroll
        for (int ks = 0; ks < 4; ++ks) {            // 4 k32 steps (32 B each)
            const uint32_t kb = ks * 32;
            uint32_t afr[2][4];
            ldsm_x4(afr[0], sbase + a_off + kb);
            ldsm_x4(afr[1], sbase + a_off + 16 * STRB + kb);
            uint32_t bfr[2][2][4];                  // [n-half][k-chunk][tile]
            #pragma unroll
            for (int h = 0; h < 2; ++h)
                #pragma unroll
                for (int c = 0; c < 2; ++c)
                    ldsm_x4(bfr[h][c], sbase + b_off + h * 32 * STRB + kb + c * 16);
            #pragma unroll
            for (int mt = 0; mt < 2; ++mt)
                #pragma unroll
                for (int h = 0; h < 2; ++h)
                    #pragma unroll
                    for (int m = 0; m < 4; ++m)
                        mma_fp8(acc[mt][h * 4 + m], afr[mt], bfr[h][0][m], bfr[h][1][m]);
        }
    }
    __syncthreads();

    // ---------------- fused ArcFace + partial softmax epilogue ----------------
    if (tid < BM) rs[tid] = 0.0f;
    __syncthreads();

    #pragma unroll
    for (int mt = 0; mt < 2; ++mt) {
        const int rl1 = wm + mt * 16 + g;
        const int rl2 = rl1 + 8;
        const int gr1 = bm + rl1;
        const int gr2 = bm + rl2;
        const int lab1 = labels[gr1];
        const int lab2 = labels[gr2];

        float s1 = 0.f, s2 = 0.f;
        #pragma unroll
        for (int nt = 0; nt < 8; ++nt) {
            // n-tile nt = h*4+m covers columns wn + h*32 + m*8
            const int noff = (nt >> 2) * 32 + (nt & 3) * 8;
            const int c0 = bn + wn + noff + 2 * tig;
            #pragma unroll
            for (int e = 0; e < 2; ++e) {
                const int c = c0 + e;
                {
                    const float cs = acc[mt][nt][e] * INV_QS2;
                    float l = cs * SCALE_F;
                    if (c == lab1) {
                        const float sine = sqrtf(fmaxf(1.0f - cs * cs, 0.0f));
                        float phi = cs * COS_M_F - sine * SIN_M_F;
                        phi = (cs > TH_F) ? phi : (cs - MM_F);
                        l = phi * SCALE_F;
                        g_llab[gr1] = l;
                    }
                    s1 += __expf(l - SCALE_F);
                }
                {
                    const float cs = acc[mt][nt][2 + e] * INV_QS2;
                    float l = cs * SCALE_F;
                    if (c == lab2) {
                        const float sine = sqrtf(fmaxf(1.0f - cs * cs, 0.0f));
                        float phi = cs * COS_M_F - sine * SIN_M_F;
                        phi = (cs > TH_F) ? phi : (cs - MM_F);
                        l = phi * SCALE_F;
                        g_llab[gr2] = l;
                    }
                    s2 += __expf(l - SCALE_F);
                }
            }
        }
        #pragma unroll
        for (int o = 1; o <= 2; o <<= 1) {
            s1 += __shfl_xor_sync(0xffffffffu, s1, o);
            s2 += __shfl_xor_sync(0xffffffffu, s2, o);
        }
        if (tig == 0) {
            atomicAdd(&rs[rl1], s1);
            atomicAdd(&rs[rl2], s2);
        }
    }
    __syncthreads();
    if (tid < BM) atomicAdd(&g_sumexp[bm + tid], rs[tid]);
}

// ---------------------------------------------------------------------------
// Kernel 3: nll per row + mean -> out[0]
// ---------------------------------------------------------------------------
__global__ void final_kernel(float* __restrict__ out) {
    const int t = threadIdx.x;
    float s = 0.f;
    for (int i = t; i < NROW; i += 256)
        s += (SCALE_F + logf(g_sumexp[i])) - g_llab[i];
    const float tot = block_sum256(s);
    if (t == 0) out[0] = tot * (1.0f / NROW);
}

// ---------------------------------------------------------------------------
extern "C" void kernel_launch(void* const* d_in, const int* in_sizes, int n_in,
                              void* d_out, int out_size) {
    const float* enc   = (const float*)d_in[0];
    const float* gamma = (const float*)d_in[1];
    const float* beta  = (const float*)d_in[2];
    const float* w     = (const float*)d_in[3];
    const int* heads   = (const int*)d_in[4];
    const int* tails   = (const int*)d_in[5];
    const int* labels  = (const int*)d_in[6];
    float* out = (float*)d_out;

    prep_kernel<<<NCLS + NROW, 256>>>(enc, gamma, beta, w, heads, tails);

    cudaFuncSetAttribute(gemm_fused_kernel,
                         cudaFuncAttributeMaxDynamicSharedMemorySize, GEMM_SMEM);
    dim3 ggrid(NCLS / BN, NROW / BM);   // (16, 8) = 128 blocks, one wave
    gemm_fused_kernel<<<ggrid, 512, GEMM_SMEM>>>(labels);

    final_kernel<<<1, 256>>>(out);
}